// round 14
// baseline (speedup 1.0000x reference)
#include <cuda_runtime.h>
#include <cuda_bf16.h>
#include <math.h>
#include <limits.h>

#define FWB    30
#define THRESH 0.015f
#define TOPK   2000
#define BATCH  32
#define HH     384
#define WW     640
#define HWSZ   (HH * WW)      // 245760
#define CH     128
#define HF     96
#define WF     160
#define HW2    (HF * WF)      // 15360
#define CHUNK  4096           // 1024 threads * 4 items

// Scratch (device globals: no allocation allowed)
__device__ int g_idx[BATCH * TOPK];
__device__ int g_cnt[BATCH];

// ---------------------------------------------------------------------------
// Kernel 1: per-batch ordered stream compaction of the first TOPK masked
// linear indices. One block per batch, 1024 threads, 4 items/thread (float4).
// Early-exits once TOPK indices are found (rows ~30-34 for these inputs).
// ---------------------------------------------------------------------------
__global__ __launch_bounds__(1024)
void select_kernel(const float* __restrict__ prob,
                   const int* __restrict__ rshape)   // int32 (JAX x64 disabled)
{
    const int b = blockIdx.x;
    const float4* p4 = (const float4*)(prob + (size_t)b * HWSZ);
    const int ylo = FWB, yhi = rshape[2 * b + 0] - FWB;
    const int xlo = FWB, xhi = rshape[2 * b + 1] - FWB;

    __shared__ int s_base;
    __shared__ int s_total;
    __shared__ int s_woff[32];

    const int t    = threadIdx.x;
    const int lane = t & 31;
    const int warp = t >> 5;
    int* out = g_idx + b * TOPK;

    if (t == 0) s_base = 0;
    __syncthreads();

    for (int chunk = 0; chunk < HWSZ; chunk += CHUNK) {
        const int i0 = chunk + t * 4;
        float4 pv = p4[i0 >> 2];
        float pa[4] = {pv.x, pv.y, pv.z, pv.w};

        int m[4];
        int cnt = 0;
        #pragma unroll
        for (int k = 0; k < 4; k++) {
            int i = i0 + k;
            int y = i / WW;
            int x = i - y * WW;
            m[k] = (y >= ylo) & (y < yhi) & (x >= xlo) & (x < xhi) &
                   (pa[k] > THRESH);
            cnt += m[k];
        }

        // warp inclusive scan of cnt
        int inc = cnt;
        #pragma unroll
        for (int off = 1; off < 32; off <<= 1) {
            int v = __shfl_up_sync(0xFFFFFFFFu, inc, off);
            if (lane >= off) inc += v;
        }
        if (lane == 31) s_woff[warp] = inc;
        __syncthreads();

        if (warp == 0) {
            int v  = s_woff[lane];
            int vi = v;
            #pragma unroll
            for (int off = 1; off < 32; off <<= 1) {
                int u = __shfl_up_sync(0xFFFFFFFFu, vi, off);
                if (lane >= off) vi += u;
            }
            s_woff[lane] = vi - v;   // exclusive warp offset
            if (lane == 31) s_total = vi;
        }
        __syncthreads();

        int pos = s_base + s_woff[warp] + (inc - cnt);
        #pragma unroll
        for (int k = 0; k < 4; k++) {
            if (m[k]) {
                if (pos < TOPK) out[pos] = i0 + k;
                pos++;
            }
        }
        __syncthreads();                 // all writers done w/ old s_base
        if (t == 0) s_base += s_total;
        __syncthreads();
        if (s_base >= TOPK) break;       // uniform (shared) -> safe break
    }

    if (t == 0) g_cnt[b] = min(s_base, TOPK);
}

// ---------------------------------------------------------------------------
// Kernel 2: bilinear descriptor gather + point scaling.
// Tile = 32 consecutive points, block = 128 threads (4 warps).
// FAST PATH (uniform y0, x-window <= 32 cols, no clamps): factor the bilinear
// interp — Phase A does the y-lerp once per (channel, column) with fully
// coalesced 128B row loads; Phase B does the x-lerp per (channel, point) from
// SMEM and issues channel-contiguous coalesced stores.
// FALLBACK (row wrap / clamp / sparse): original scalar 4-tap path.
// ---------------------------------------------------------------------------
__global__ __launch_bounds__(128)
void gather_kernel(const float* __restrict__ feat,
                   const float* __restrict__ ratio,
                   float* __restrict__ pts,
                   float* __restrict__ des)
{
    const int b    = blockIdx.y;
    const int p0   = blockIdx.x * 32;
    const int t    = threadIdx.x;
    const int lane = t & 31;
    const int w    = t >> 5;
    const unsigned FULL = 0xFFFFFFFFu;

    __shared__ float  s_buf[CH * 33];     // 16896 B, dual-view
    __shared__ float4 s_pw[32];           // w0, w1, dx0(bits), dx1(bits)
    float (*s_row)[33]     = (float (*)[33])s_buf;      // fast:   [CH][33]
    float (*s_des)[CH + 1] = (float (*)[CH + 1])s_buf;  // fallback:[32][129]

    // ---- Phase 0: per-point data (lane = point; identical in all warps) ----
    const int cnt = g_cnt[b];
    const int P   = p0 + lane;
    const bool valid = (P < TOPK) && (P < cnt);

    const int idx = valid ? g_idx[b * TOPK + P] : 0;
    const int yi  = idx / WW;
    const int xi  = idx - yi * WW;

    const float fx = (float)xi * 0.25f;
    const float fy = (float)yi * 0.25f;
    const int x0 = (int)floorf(fx);
    const int y0 = (int)floorf(fy);
    // JAX gather clamps out-of-range indices (fallback path only)
    const int x0c = min(max(x0, 0), WF - 1);
    const int x1c = min(max(x0 + 1, 0), WF - 1);
    const int y0c = min(max(y0, 0), HF - 1);
    const int y1c = min(max(y0 + 1, 0), HF - 1);

    const float ax = fx - (float)x0;   // exact (quarter multiples)
    const float ay = fy - (float)y0;

    // Block-uniform fast-path decision (all warps see identical point data)
    unsigned vm = __ballot_sync(FULL, valid);
    bool fast;
    int  xwlo = 0, y0r = 0;
    float dy = 0.0f;
    if (vm != 0) {
        const int src = __ffs(vm) - 1;
        y0r = __shfl_sync(FULL, y0, src);
        dy  = __shfl_sync(FULL, ay, src);
        bool ok = (!valid) || ((y0 == y0r) && (x0 >= 0) && (x0 + 1 <= WF - 1));
        int xmn = valid ? x0 : INT_MAX;
        int xmx = valid ? (x0 + 1) : INT_MIN;
        #pragma unroll
        for (int o = 16; o; o >>= 1) {
            xmn = min(xmn, __shfl_xor_sync(FULL, xmn, o));
            xmx = max(xmx, __shfl_xor_sync(FULL, xmx, o));
        }
        fast = __all_sync(FULL, ok) && (xmx - xmn <= 31) &&
               (y0r >= 0) && (y0r + 1 <= HF - 1);
        xwlo = xmn;
    } else {
        fast = true;   // all-invalid tile: emit zeros via zero weights
    }

    if (w == 0) {
        const float scale = valid ? 1.0f : 0.0f;
        float4 pw;
        pw.x = (1.0f - ax) * scale;
        pw.y = ax * scale;
        pw.z = __int_as_float(valid ? (x0 - xwlo) : 0);
        pw.w = __int_as_float(valid ? (x0 + 1 - xwlo) : 0);
        s_pw[lane] = pw;

        if (P < TOPK) {
            const float r  = ratio[b];
            const float px = valid ? (float)xi / r : 0.0f;
            const float py = valid ? (float)yi / r : 0.0f;
            *(float2*)(pts + ((size_t)b * TOPK + P) * 2) = make_float2(px, py);
        }
    }

    const float* fb = feat + (size_t)b * CH * HW2;

    if (fast) {
        // ---- Phase A: y-lerp rows into SMEM (lane = column, warp = 32 ch) ----
        const int colc = min(xwlo + lane, WF - 1);
        const float* f0 = fb + y0r * WF + colc;          // +WF for row y0+1
        const float ody = 1.0f - dy;
        #pragma unroll 8
        for (int i = 0; i < 32; i++) {
            const int c = w * 32 + i;
            const float r0 = f0[(size_t)c * HW2];
            const float r1 = f0[(size_t)c * HW2 + WF];
            s_row[c][lane] = r0 * ody + r1 * dy;
        }
        __syncthreads();

        // ---- Phase B: x-lerp + coalesced stores (t = channel) ----
        const float* rowt = s_row[t];
        float* dbase = des + ((size_t)b * TOPK + p0) * CH + t;
        #pragma unroll 8
        for (int p = 0; p < 32; p++) {
            if (p0 + p >= TOPK) break;
            const float4 pw = s_pw[p];                   // LDS.128 broadcast
            const int dx0 = __float_as_int(pw.z);
            const int dx1 = __float_as_int(pw.w);
            dbase[(size_t)p * CH] = rowt[dx0] * pw.x + rowt[dx1] * pw.y;
        }
    } else {
        // ---- Fallback: scalar 4-tap gather (lane = point, warp = 32 ch) ----
        const float wa = (1.0f - ax) * (1.0f - ay);
        const float wb = (1.0f - ax) * ay;
        const float wc = ax * (1.0f - ay);
        const float wd = ax * ay;
        const int oa = y0c * WF + x0c;
        const int ob = y1c * WF + x0c;
        const int oc = y0c * WF + x1c;
        const int od = y1c * WF + x1c;

        #pragma unroll 8
        for (int c = w; c < CH; c += 4) {
            const float* fc = fb + (size_t)c * HW2;
            float Ia = valid ? fc[oa] : 0.0f;
            float Ib = valid ? fc[ob] : 0.0f;
            float Ic = valid ? fc[oc] : 0.0f;
            float Id = valid ? fc[od] : 0.0f;
            s_des[lane][c] = Ia * wa + Ib * wb + Ic * wc + Id * wd;
        }
        __syncthreads();

        #pragma unroll 4
        for (int i = 0; i < 32; i++) {
            const int P2 = p0 + i;
            if (P2 >= TOPK) break;
            des[((size_t)b * TOPK + P2) * CH + t] = s_des[i][t];
        }
    }
}

// ---------------------------------------------------------------------------
extern "C" void kernel_launch(void* const* d_in, const int* in_sizes, int n_in,
                              void* d_out, int out_size)
{
    const float* prob   = (const float*)d_in[0];      // (32,1,384,640) f32
    const float* feat   = (const float*)d_in[1];      // (32,128,96,160) f32
    const float* ratio  = (const float*)d_in[2];      // (32,1) f32
    const int*   rshape = (const int*)d_in[3];        // (32,2) int32

    float* pts = (float*)d_out;                       // (32,2000,2)
    float* des = pts + (size_t)BATCH * TOPK * 2;      // (32,2000,128)

    select_kernel<<<BATCH, 1024>>>(prob, rshape);

    dim3 grid((TOPK + 31) / 32, BATCH);               // (63, 32)
    gather_kernel<<<grid, 128>>>(feat, ratio, pts, des);
}